// round 15
// baseline (speedup 1.0000x reference)
#include <cuda_runtime.h>
#include <cuda_bf16.h>
#include <cstdint>

#define NN 50000
#define NE 800000
#define FIN 500
#define HD 96

// ---------------- device scratch (no allocations allowed) ----------------
__device__ int   g_cnt_out[NN];
__device__ int   g_cnt_in[NN];
__device__ float g_norm_out[NN];
__device__ float g_norm_in[NN];
__device__ int   g_coff[NN + 1];
__device__ int   g_cursor[NN];
__device__ int   g_csr_src[NE];
__device__ int   g_bsums[64];
__device__ float g_bufA[2 * NN * HD];   // GEMM outputs
__device__ float g_bufB[2 * NN * HD];   // SpMM outputs (layer-1 activations)
__device__ float g_wv[HD];
__device__ float g_bmsum;

// ---------------- degrees / norms ----------------
__global__ void k_zero() {
    int i = blockIdx.x * blockDim.x + threadIdx.x;
    if (i < NN) { g_cnt_out[i] = 0; g_cnt_in[i] = 0; }
}

__global__ void k_deg(const int* __restrict__ src, const int* __restrict__ dst) {
    int e = blockIdx.x * blockDim.x + threadIdx.x;
    if (e < NE) {
        atomicAdd(&g_cnt_out[src[e]], 1);
        atomicAdd(&g_cnt_in[dst[e]], 1);
    }
}

__global__ void k_norm() {
    int i = blockIdx.x * blockDim.x + threadIdx.x;
    if (i < NN) {
        g_norm_out[i] = rsqrtf((float)max(g_cnt_out[i], 1));
        g_norm_in[i]  = rsqrtf((float)max(g_cnt_in[i], 1));
    }
}

// ---------------- CSR build ----------------
__global__ void k_scan_part() {
    __shared__ int s[1024];
    int t = threadIdx.x;
    int i = blockIdx.x * 1024 + t;
    int c = (i < NN) ? g_cnt_in[i] : 0;
    s[t] = c;
    __syncthreads();
    for (int off = 1; off < 1024; off <<= 1) {
        int v = (t >= off) ? s[t - off] : 0;
        __syncthreads();
        s[t] += v;
        __syncthreads();
    }
    if (i < NN) g_coff[i] = s[t] - c;
    if (t == 1023) g_bsums[blockIdx.x] = s[t];
}

__global__ void k_scan_top(int nb) {
    if (threadIdx.x == 0) {
        int run = 0;
        for (int b = 0; b < nb; b++) { int v = g_bsums[b]; g_bsums[b] = run; run += v; }
    }
}

__global__ void k_scan_add() {
    int i = blockIdx.x * 1024 + threadIdx.x;
    if (i < NN) {
        int v = g_coff[i] + g_bsums[blockIdx.x];
        g_coff[i] = v;
        g_cursor[i] = v;
    }
    if (i == 0) g_coff[NN] = NE;
}

__global__ void k_scatter(const int* __restrict__ src, const int* __restrict__ dst) {
    int e = blockIdx.x * blockDim.x + threadIdx.x;
    if (e < NE) {
        int d = dst[e];
        int p = atomicAdd(&g_cursor[d], 1);
        g_csr_src[p] = src[e];
    }
}

// ---------------- Wm row-sums + bm sum ----------------
__global__ void k_wv(const float* __restrict__ Wm, const float* __restrict__ bm) {
    int t = threadIdx.x;
    if (t < HD) {
        float s = 0.f;
        for (int j = 0; j < HD; j++) s += Wm[t * HD + j];
        g_wv[t] = s;
        if (t == 0) {
            float bs = 0.f;
            for (int j = 0; j < HD; j++) bs += bm[j];
            g_bmsum = bs;
        }
    }
}

// ---------------- bf16-split GEMM via mma.sync + ldmatrix ------------------
// C = A @ W [* norm_out if SCALE], split: A=Ah+Al, W=Wh+Wl,
// acc += Ah*Wh + Ah*Wl + Al*Wh (fp32 acc).
// Block 64x96, 8 warps (4 wm x 2 wn), warp tile 16x48 = 1x6 m16n8k16 tiles.
// SMEM rows stride 80B (40 bf16, 32 used) — conflict-free for ldmatrix.
// Double-buffered, register prefetch, 3 CTAs/SM.

__device__ __forceinline__ void mma16816(float* d,
                                         uint32_t a0, uint32_t a1, uint32_t a2, uint32_t a3,
                                         uint32_t b0, uint32_t b1) {
    asm volatile(
        "mma.sync.aligned.m16n8k16.row.col.f32.bf16.bf16.f32 "
        "{%0,%1,%2,%3}, {%4,%5,%6,%7}, {%8,%9}, {%0,%1,%2,%3};"
        : "+f"(d[0]), "+f"(d[1]), "+f"(d[2]), "+f"(d[3])
        : "r"(a0), "r"(a1), "r"(a2), "r"(a3), "r"(b0), "r"(b1));
}

__device__ __forceinline__ void ldsm4(uint32_t* r, uint32_t addr) {
    asm volatile("ldmatrix.sync.aligned.m8n8.x4.shared.b16 {%0,%1,%2,%3}, [%4];"
        : "=r"(r[0]), "=r"(r[1]), "=r"(r[2]), "=r"(r[3]) : "r"(addr));
}

__device__ __forceinline__ uint32_t pk2b(__nv_bfloat16 a, __nv_bfloat16 b) {
    __nv_bfloat162 t(a, b);
    return *(uint32_t*)&t;
}

#define AB 5120                  // 64 rows * 80 B
#define BB 7680                  // 96 rows * 80 B
#define OFF_AL AB
#define OFF_BH (2 * AB)
#define OFF_BL (2 * AB + BB)
#define BUFB (2 * AB + 2 * BB)   // 25600 per buffer
#define SMEM_MMA (2 * BUFB)      // 51200

template <int K, bool SCALE>
__global__ __launch_bounds__(256, 3)
void k_mma(const float* __restrict__ Ain, const float* __restrict__ W, int M) {
    constexpr int NC = (K + 31) / 32;
    extern __shared__ char sm[];
    const uint32_t sbase = (uint32_t)__cvta_generic_to_shared(sm);

    const float* __restrict__ A = SCALE ? (const float*)g_bufB : Ain;
    const int tid = threadIdx.x;
    const int wid = tid >> 5;
    const int lane = tid & 31;
    const int wm = wid >> 1;          // 0..3 (16 rows each)
    const int wn = wid & 1;           // 0..1 (48 cols each)
    const int m0 = blockIdx.x * 64;

    float4 ra[2];
    float  rb[12];

    auto loadA = [&](int k0) {
#pragma unroll
        for (int l = 0; l < 2; l++) {
            int j = tid + l * 256;
            int r = j >> 3;
            int q = j & 7;
            int m = m0 + r;
            int col = k0 + q * 4;
            ra[l] = (m < M && col + 4 <= K)
                        ? *(const float4*)&A[(long)m * K + col]
                        : make_float4(0.f, 0.f, 0.f, 0.f);
        }
    };
    auto loadB = [&](int k0) {
#pragma unroll
        for (int l = 0; l < 12; l++) {
            int j = tid + l * 256;
            int k = j / HD;
            int n = j - k * HD;
            rb[l] = (k0 + k < K) ? W[(long)(k0 + k) * HD + n] : 0.f;
        }
    };
    auto store = [&](int buf) {
        char* pAH = sm + buf * BUFB;
        char* pAL = pAH + OFF_AL;
        char* pBH = pAH + OFF_BH - OFF_AL + AB;   // = pAH + 2*AB
        char* pBL = pAH + OFF_BL;
        pBH = pAH + OFF_BH;
#pragma unroll
        for (int l = 0; l < 2; l++) {
            int j = tid + l * 256;
            int r = j >> 3;
            int q = j & 7;
            float4 v = ra[l];
            __nv_bfloat16 hx = __float2bfloat16(v.x), hy = __float2bfloat16(v.y);
            __nv_bfloat16 hz = __float2bfloat16(v.z), hw = __float2bfloat16(v.w);
            __nv_bfloat16 lx = __float2bfloat16(v.x - __bfloat162float(hx));
            __nv_bfloat16 ly = __float2bfloat16(v.y - __bfloat162float(hy));
            __nv_bfloat16 lz = __float2bfloat16(v.z - __bfloat162float(hz));
            __nv_bfloat16 lw = __float2bfloat16(v.w - __bfloat162float(hw));
            *(uint2*)(pAH + r * 80 + q * 8) = make_uint2(pk2b(hx, hy), pk2b(hz, hw));
            *(uint2*)(pAL + r * 80 + q * 8) = make_uint2(pk2b(lx, ly), pk2b(lz, lw));
        }
#pragma unroll
        for (int l = 0; l < 12; l++) {
            int j = tid + l * 256;
            int k = j / HD;
            int n = j - k * HD;
            float v = rb[l];
            __nv_bfloat16 h = __float2bfloat16(v);
            __nv_bfloat16 lo = __float2bfloat16(v - __bfloat162float(h));
            *(__nv_bfloat16*)(pBH + n * 80 + k * 2) = h;
            *(__nv_bfloat16*)(pBL + n * 80 + k * 2) = lo;
        }
    };

    float acc[6][4];
#pragma unroll
    for (int b = 0; b < 6; b++)
#pragma unroll
        for (int c = 0; c < 4; c++) acc[b][c] = 0.f;

    loadA(0);
    loadB(0);
    store(0);
    __syncthreads();

    // ldmatrix per-lane address components
    const uint32_t a_lane = (uint32_t)((wm * 16 + (lane & 15)) * 80 + (lane >> 4) * 16);
    const uint32_t b_lane = (uint32_t)(((lane & 7) + ((lane >> 4) << 3)) * 80 +
                                       ((lane >> 3) & 1) * 16 + wn * 48 * 80);

    int buf = 0;
    for (int c = 0; c < NC; c++) {
        if (c + 1 < NC) {
            loadA((c + 1) * 32);
            loadB((c + 1) * 32);
        }
        const uint32_t base = sbase + buf * BUFB;
        const uint32_t aH = base + a_lane;
        const uint32_t aL = aH + OFF_AL;
        const uint32_t bH = base + OFF_BH + b_lane;
        const uint32_t bL = bH + BB;
#pragma unroll
        for (int ks = 0; ks < 2; ks++) {
            const uint32_t ko = ks * 32;
            uint32_t ah[4], al[4];
            ldsm4(ah, aH + ko);
            ldsm4(al, aL + ko);
#pragma unroll
            for (int tp = 0; tp < 3; tp++) {
                uint32_t bh[4], bl[4];
                ldsm4(bh, bH + tp * 1280 + ko);
                ldsm4(bl, bL + tp * 1280 + ko);
                float* a0 = acc[tp * 2];
                float* a1 = acc[tp * 2 + 1];
                mma16816(a0, ah[0], ah[1], ah[2], ah[3], bh[0], bh[1]);
                mma16816(a1, ah[0], ah[1], ah[2], ah[3], bh[2], bh[3]);
                mma16816(a0, ah[0], ah[1], ah[2], ah[3], bl[0], bl[1]);
                mma16816(a1, ah[0], ah[1], ah[2], ah[3], bl[2], bl[3]);
                mma16816(a0, al[0], al[1], al[2], al[3], bh[0], bh[1]);
                mma16816(a1, al[0], al[1], al[2], al[3], bh[2], bh[3]);
            }
        }
        if (c + 1 < NC) {
            store(buf ^ 1);
            __syncthreads();
            buf ^= 1;
        }
    }

    // epilogue: warp rows r0 = wm*16 + lane/4, r1 = +8
    {
        int r0 = m0 + wm * 16 + (lane >> 2);
        int r1 = r0 + 8;
        float s0 = 1.f, s1 = 1.f;
        if (SCALE) {
            if (r0 < M) s0 = g_norm_out[(r0 < NN) ? r0 : r0 - NN];
            if (r1 < M) s1 = g_norm_out[(r1 < NN) ? r1 : r1 - NN];
        }
#pragma unroll
        for (int tn = 0; tn < 6; tn++) {
            int col = wn * 48 + tn * 8 + (lane & 3) * 2;
            float* a = acc[tn];
            if (r0 < M) *(float2*)&g_bufA[(long)r0 * HD + col] = make_float2(a[0] * s0, a[1] * s0);
            if (r1 < M) *(float2*)&g_bufA[(long)r1 * HD + col] = make_float2(a[2] * s1, a[3] * s1);
        }
    }
}

// ---------------- SpMM block-per-(view,node): 24 chunks x 4 edge slots ------
template <bool LAST>
__global__ __launch_bounds__(96)
void k_spmm(const int* __restrict__ perm,
            const float* __restrict__ bvec, const float* __restrict__ avec,
            float* __restrict__ out) {
    int b = blockIdx.x;
    int v = (b >= NN) ? 1 : 0;
    int i = b - v * NN;
    int t = threadIdx.x;
    int c = t % 24;
    int slot = t / 24;

    int beg = g_coff[i];
    int end = g_coff[i + 1];

    float4 acc = make_float4(0.f, 0.f, 0.f, 0.f);
    for (int e = beg + slot; e < end; e += 4) {
        int s = g_csr_src[e];
        const float* row;
        float sc = 1.f;
        if (!LAST) {
            int rs = v ? perm[s] : s;
            sc = g_norm_out[s];
            row = g_bufA + (long)rs * HD;
        } else {
            row = g_bufA + (long)(v * NN + s) * HD;
        }
        float4 p = *(const float4*)(row + c * 4);
        if (!LAST) {
            acc.x += sc * p.x; acc.y += sc * p.y; acc.z += sc * p.z; acc.w += sc * p.w;
        } else {
            acc.x += p.x; acc.y += p.y; acc.z += p.z; acc.w += p.w;
        }
    }

    __shared__ float4 red[96];
    __shared__ float sred[24];
    red[t] = acc;
    __syncthreads();
    if (slot == 0) {
        float4 r = red[c];
        float4 r1 = red[c + 24];
        float4 r2 = red[c + 48];
        float4 r3 = red[c + 72];
        r.x += r1.x + r2.x + r3.x;
        r.y += r1.y + r2.y + r3.y;
        r.z += r1.z + r2.z + r3.z;
        r.w += r1.w + r2.w + r3.w;

        float ni = g_norm_in[i];
        float4 bb = *(const float4*)(bvec + c * 4);
        float4 aa = *(const float4*)(avec + c * 4);
        float4 h;
        h.x = r.x * ni + bb.x;
        h.y = r.y * ni + bb.y;
        h.z = r.z * ni + bb.z;
        h.w = r.w * ni + bb.w;
        h.x = (h.x >= 0.f) ? h.x : aa.x * h.x;
        h.y = (h.y >= 0.f) ? h.y : aa.y * h.y;
        h.z = (h.z >= 0.f) ? h.z : aa.z * h.z;
        h.w = (h.w >= 0.f) ? h.w : aa.w * h.w;
        if (!LAST) {
            *(float4*)(g_bufB + (long)(v * NN + i) * HD + c * 4) = h;
        } else {
            float4 wv = *(const float4*)(g_wv + c * 4);
            sred[c] = h.x * wv.x + h.y * wv.y + h.z * wv.z + h.w * wv.w;
        }
    }
    if (LAST) {
        __syncthreads();
        if (t == 0) {
            float s = 0.f;
#pragma unroll
            for (int j = 0; j < 24; j++) s += sred[j];
            out[v * NN + i] = s + g_bmsum;
        }
    }
}

// ---------------- side stream + events (static init; never destroyed) ------
struct SideStream {
    cudaStream_t s = nullptr;
    cudaEvent_t fork = nullptr, join = nullptr;
    SideStream() {
        cudaStreamCreateWithFlags(&s, cudaStreamNonBlocking);
        cudaEventCreateWithFlags(&fork, cudaEventDisableTiming);
        cudaEventCreateWithFlags(&join, cudaEventDisableTiming);
    }
};
static SideStream g_ss;

// ---------------- launch ----------------
extern "C" void kernel_launch(void* const* d_in, const int* in_sizes, int n_in,
                              void* d_out, int out_size) {
    const float* x   = (const float*)d_in[0];
    const int*   src = (const int*)d_in[1];
    const int*   dst = (const int*)d_in[2];
    const int*   perm= (const int*)d_in[3];
    const float* W1  = (const float*)d_in[4];
    const float* b1  = (const float*)d_in[5];
    const float* a1  = (const float*)d_in[6];
    const float* W2  = (const float*)d_in[7];
    const float* b2  = (const float*)d_in[8];
    const float* a2  = (const float*)d_in[9];
    const float* Wm  = (const float*)d_in[10];
    const float* bm  = (const float*)d_in[11];
    float* out = (float*)d_out;

    cudaFuncSetAttribute(k_mma<FIN, false>,
                         cudaFuncAttributeMaxDynamicSharedMemorySize, SMEM_MMA);
    cudaFuncSetAttribute(k_mma<HD, true>,
                         cudaFuncAttributeMaxDynamicSharedMemorySize, SMEM_MMA);

    // fork side stream off the capture stream
    cudaEventRecord(g_ss.fork, 0);
    cudaStreamWaitEvent(g_ss.s, g_ss.fork, 0);

    // prep on the side stream, overlapped with GEMM1
    k_zero<<<(NN + 255) / 256, 256, 0, g_ss.s>>>();
    k_deg<<<(NE + 255) / 256, 256, 0, g_ss.s>>>(src, dst);
    k_norm<<<(NN + 255) / 256, 256, 0, g_ss.s>>>();

    // launch 3 (main stream): layer-1 GEMM (ncu capture slot)
    k_mma<FIN, false><<<(NN + 63) / 64, 256, SMEM_MMA>>>(x, W1, NN);

    int nb = (NN + 1023) / 1024;
    k_scan_part<<<nb, 1024, 0, g_ss.s>>>();
    k_scan_top<<<1, 32, 0, g_ss.s>>>(nb);
    k_scan_add<<<nb, 1024, 0, g_ss.s>>>();
    k_scatter<<<(NE + 255) / 256, 256, 0, g_ss.s>>>(src, dst);
    k_wv<<<1, HD, 0, g_ss.s>>>(Wm, bm);

    // join: SpMM needs both GEMM1 (main) and CSR/norms (side)
    cudaEventRecord(g_ss.join, g_ss.s);
    cudaStreamWaitEvent(0, g_ss.join, 0);

    // layer 1 SpMM (norm_out folded in, both views gather from P = x@W1)
    k_spmm<false><<<2 * NN, 96>>>(perm, b1, a1, nullptr);

    // layer 2: bufA = norm_out * (bufB @ W2), then SpMM fused with readout
    k_mma<HD, true><<<(2 * NN + 63) / 64, 256, SMEM_MMA>>>(nullptr, W2, 2 * NN);
    k_spmm<true><<<2 * NN, 96>>>(perm, b2, a2, out);
}